// round 2
// baseline (speedup 1.0000x reference)
#include <cuda_runtime.h>

#define KCTX 64
#define DIM  128
#define CAND 256
#define DSLEN 200
#define EPS 1e-8f
#define PITCH 132   // smem row pitch in floats (528B; /16 = 33, odd -> conflict-free LDS.128)

__device__ float g_A[KCTX * DIM];
__device__ float g_AM[KCTX * DIM];

// ---- index dtype sniffing: reference claims int64 but JAX w/o x64 emits int32 ----
__device__ __forceinline__ bool idx_is64(const void* p, long long V) {
    const long long* q = (const long long*)p;
    bool ok = true;
#pragma unroll
    for (int i = 0; i < 8; i++) {
        long long v = q[i];
        if (v < 0 || v >= V) ok = false;
    }
    return ok;
}
__device__ __forceinline__ long long load_idx(const void* p, long long i, bool is64) {
    return is64 ? ((const long long*)p)[i] : (long long)((const int*)p)[i];
}

// -------- prep: A = table[t1_ctx]; AM = A @ att_mat --------
__global__ __launch_bounds__(DIM) void prep_kernel(
    const float* __restrict__ table,
    const float* __restrict__ att_mat,
    const void* __restrict__ t1_ctx,
    long long V)
{
    __shared__ float sa[DIM];
    const bool is64 = idx_is64(t1_ctx, V);
    int k = blockIdx.x;
    int j = threadIdx.x;
    long long row = load_idx(t1_ctx, k, is64);
    float a = table[row * DIM + j];
    g_A[k * DIM + j] = a;
    sa[j] = a;
    __syncthreads();
    float acc = 0.f;
#pragma unroll 8
    for (int d = 0; d < DIM; ++d)
        acc = fmaf(sa[d], att_mat[d * DIM + j], acc);
    g_AM[k * DIM + j] = acc;
}

// -------- main: one CTA per candidate --------
__global__ __launch_bounds__(256) void cand_kernel(
    const float* __restrict__ table,
    const float* __restrict__ str_t1,
    const float* __restrict__ str_t2s,
    const float* __restrict__ W_bi,
    const float* __restrict__ b_bi,
    const void* __restrict__ t2_ctx,
    float* __restrict__ out,
    long long V)
{
    extern __shared__ float smem[];
    float* sAM = smem;                    // KCTX * PITCH
    float* sB  = smem + KCTX * PITCH;     // KCTX * PITCH

    __shared__ float rowsum[KCTX];
    __shared__ float colsum[KCTX];
    __shared__ float rows_w[KCTX];
    __shared__ float cols_w[KCTX];
    __shared__ float newA[DIM];
    __shared__ float newB[DIM];
    __shared__ float tvec[DIM];
    __shared__ float red3[3][8];
    __shared__ float s_con, s_str;

    const int tid = threadIdx.x;
    const int c   = blockIdx.x;
    const bool is64 = idx_is64(t2_ctx, V);

    // load AM (contiguous 32KB, L2-hot) into padded smem
    for (int i = tid; i < KCTX * DIM; i += 256) {
        int k = i >> 7, d = i & 127;
        sAM[k * PITCH + d] = g_AM[i];
    }
    // gather B rows via float4
    {
        const long long base = (long long)c * KCTX;
        for (int i = tid; i < KCTX * (DIM / 4); i += 256) {
            int k = i >> 5, q = i & 31;
            long long r = load_idx(t2_ctx, base + k, is64);
            float4 v = ((const float4*)(table + r * DIM))[q];
            float* dst = &sB[k * PITCH + q * 4];
            dst[0] = v.x; dst[1] = v.y; dst[2] = v.z; dst[3] = v.w;
        }
    }
    if (tid < KCTX) colsum[tid] = 0.f;
    __syncthreads();

    // ---- 64x64x128 GEMM, 4x4 per thread; rows of S = ty+16i, cols = tx+16j ----
    const int tx = tid & 15;
    const int ty = tid >> 4;
    float acc[4][4];
#pragma unroll
    for (int i = 0; i < 4; i++)
#pragma unroll
        for (int j = 0; j < 4; j++) acc[i][j] = 0.f;

#pragma unroll 4
    for (int d = 0; d < DIM; d += 4) {
        float4 av[4], bv[4];
#pragma unroll
        for (int i = 0; i < 4; i++)
            av[i] = *(const float4*)&sAM[(ty + 16 * i) * PITCH + d];
#pragma unroll
        for (int j = 0; j < 4; j++)
            bv[j] = *(const float4*)&sB[(tx + 16 * j) * PITCH + d];
#pragma unroll
        for (int i = 0; i < 4; i++)
#pragma unroll
            for (int j = 0; j < 4; j++) {
                acc[i][j] = fmaf(av[i].x, bv[j].x, acc[i][j]);
                acc[i][j] = fmaf(av[i].y, bv[j].y, acc[i][j]);
                acc[i][j] = fmaf(av[i].z, bv[j].z, acc[i][j]);
                acc[i][j] = fmaf(av[i].w, bv[j].w, acc[i][j]);
            }
    }

    // tanh + row/col partial sums (S never materialized)
    float pr[4] = {0.f, 0.f, 0.f, 0.f};
    float pc[4] = {0.f, 0.f, 0.f, 0.f};
#pragma unroll
    for (int i = 0; i < 4; i++)
#pragma unroll
        for (int j = 0; j < 4; j++) {
            float t = tanhf(acc[i][j]);
            pr[i] += t;
            pc[j] += t;
        }

    // row sums: reduce over tx within the 16-lane half-warp
#pragma unroll
    for (int i = 0; i < 4; i++) {
        float v = pr[i];
#pragma unroll
        for (int off = 1; off < 16; off <<= 1)
            v += __shfl_xor_sync(0xffffffffu, v, off);
        if (tx == 0) rowsum[ty + 16 * i] = v;
    }
    // col sums: combine the two ty's in this warp, then cross-warp smem atomics
#pragma unroll
    for (int j = 0; j < 4; j++) {
        float v = pc[j] + __shfl_xor_sync(0xffffffffu, pc[j], 16);
        if ((tid & 16) == 0)
            atomicAdd(&colsum[tx + 16 * j], v);
    }
    __syncthreads();

    // ---- softmaxes over k (length 64): warp 0 -> rows, warp 1 -> cols ----
    if (tid < 64) {
        const float* src = (tid < 32) ? rowsum : colsum;
        float* dst       = (tid < 32) ? rows_w : cols_w;
        int l = tid & 31;
        float v0 = src[l] * (1.f / 64.f);
        float v1 = src[l + 32] * (1.f / 64.f);
        float m = fmaxf(v0, v1);
#pragma unroll
        for (int off = 16; off > 0; off >>= 1)
            m = fmaxf(m, __shfl_xor_sync(0xffffffffu, m, off));
        float e0 = expf(v0 - m), e1 = expf(v1 - m);
        float s = e0 + e1;
#pragma unroll
        for (int off = 16; off > 0; off >>= 1)
            s += __shfl_xor_sync(0xffffffffu, s, off);
        float inv = 1.f / s;
        dst[l] = e0 * inv;
        dst[l + 32] = e1 * inv;
    }

    // ---- string branch (all warps help) ----
    {
        float p = 0.f, q1 = 0.f, q2 = 0.f;
        for (int i = tid; i < DSLEN; i += 256) {
            float x = str_t1[i];
            float y = str_t2s[c * DSLEN + i];
            p  = fmaf(x, y, p);
            q1 = fmaf(x, x, q1);
            q2 = fmaf(y, y, q2);
        }
#pragma unroll
        for (int off = 16; off > 0; off >>= 1) {
            p  += __shfl_xor_sync(0xffffffffu, p,  off);
            q1 += __shfl_xor_sync(0xffffffffu, q1, off);
            q2 += __shfl_xor_sync(0xffffffffu, q2, off);
        }
        int w = tid >> 5;
        if ((tid & 31) == 0) {
            red3[0][w] = p; red3[1][w] = q1; red3[2][w] = q2;
        }
    }
    __syncthreads();
    if (tid == 0) {
        float p = 0.f, q1 = 0.f, q2 = 0.f;
#pragma unroll
        for (int w = 0; w < 8; w++) { p += red3[0][w]; q1 += red3[1][w]; q2 += red3[2][w]; }
        float n1 = fmaxf(sqrtf(q1), EPS);
        float n2 = fmaxf(sqrtf(q2), EPS);
        s_str = p / (n1 * n2);
    }

    // ---- new_A = rows @ A ; new_B = cols . B ----
    if (tid < DIM) {
        float a = 0.f, b = 0.f;
#pragma unroll 8
        for (int k = 0; k < KCTX; k++) {
            a = fmaf(rows_w[k], g_A[k * DIM + tid], a);
            b = fmaf(cols_w[k], sB[k * PITCH + tid], b);
        }
        newA[tid] = a;
        newB[tid] = b;
    }
    __syncthreads();

    // ---- bilinear: tvec[e] = sum_d newA[d] * W[d,e];  con = tvec . newB + b ----
    if (tid < DIM) {
        float t = 0.f;
#pragma unroll 8
        for (int d = 0; d < DIM; d++)
            t = fmaf(newA[d], W_bi[d * DIM + tid], t);
        tvec[tid] = t * newB[tid];
    }
    __syncthreads();
    if (tid < 32) {
        float v = tvec[tid] + tvec[tid + 32] + tvec[tid + 64] + tvec[tid + 96];
#pragma unroll
        for (int off = 16; off > 0; off >>= 1)
            v += __shfl_xor_sync(0xffffffffu, v, off);
        if (tid == 0) s_con = v + b_bi[0];
    }
    __syncthreads();

    if (tid == 0)
        out[c] = 0.5f * s_str + 0.5f * s_con;
}

extern "C" void kernel_launch(void* const* d_in, const int* in_sizes, int n_in,
                              void* d_out, int out_size)
{
    const float* table   = (const float*)d_in[0];
    const float* str_t1  = (const float*)d_in[1];
    const float* str_t2s = (const float*)d_in[2];
    const float* att_mat = (const float*)d_in[3];
    const float* W_bi    = (const float*)d_in[4];
    const float* b_bi    = (const float*)d_in[5];
    const void*  t1_ctx  = (const void*)d_in[6];
    const void*  t2_ctx  = (const void*)d_in[7];
    float* out = (float*)d_out;

    long long V = (long long)in_sizes[0] / DIM;

    cudaFuncSetAttribute(cand_kernel,
                         cudaFuncAttributeMaxDynamicSharedMemorySize,
                         2 * KCTX * PITCH * (int)sizeof(float));

    prep_kernel<<<KCTX, DIM>>>(table, att_mat, t1_ctx, V);
    cand_kernel<<<CAND, 256, 2 * KCTX * PITCH * (int)sizeof(float)>>>(
        table, str_t1, str_t2s, W_bi, b_bi, t2_ctx, out, V);
}